// round 1
// baseline (speedup 1.0000x reference)
#include <cuda_runtime.h>
#include <cuda_bf16.h>

// Problem constants
#define kT   32768
#define kL   3
#define kCLS 1024

// Scratch (no cudaMalloc allowed) — device globals
__device__ float g_outs[kT];      // top-layer hidden states
__device__ float g_logits[kCLS];  // pre-softmax logits

// ---------------------------------------------------------------------------
// Fast-but-accurate activations (EX2 + RCP based, ~2 ulp; tanh.approx would be
// ~6e-4 abs error which can amplify through the 32768-step recurrence).
// ---------------------------------------------------------------------------
__device__ __forceinline__ float f_sigmoid(float x) {
    float e = __expf(-x);
    return __fdividef(1.0f, 1.0f + e);
}
__device__ __forceinline__ float f_tanh(float x) {
    float e = __expf(2.0f * x);
    return 1.0f - __fdividef(2.0f, e + 1.0f);
}

// ---------------------------------------------------------------------------
// LSTM wavefront kernel: 1 warp. Lane l (l<3) runs layer l at timestep
// t = iter - 2*l (lag-2 pipeline so the cross-layer shfl edge has a full
// iteration of slack and never sits on the recurrence critical cycle).
// Lanes 3..31 shadow layer 2 harmlessly (never commit/store).
// ---------------------------------------------------------------------------
__global__ void __launch_bounds__(32, 1)
lstm_kernel(const float* __restrict__ x,
            const float* __restrict__ h0,
            const float* __restrict__ c0,
            const float* __restrict__ w_ih,
            const float* __restrict__ w_hh,
            const float* __restrict__ b_ih,
            const float* __restrict__ b_hh)
{
    const int lane = threadIdx.x & 31;
    const int ll   = (lane < kL) ? lane : (kL - 1);

    // Per-layer parameters (w_ih[l,4,1] -> l*4+k; biases fused)
    const float wi0 = w_ih[ll*4+0], wi1 = w_ih[ll*4+1], wi2 = w_ih[ll*4+2], wi3 = w_ih[ll*4+3];
    const float wh0 = w_hh[ll*4+0], wh1 = w_hh[ll*4+1], wh2 = w_hh[ll*4+2], wh3 = w_hh[ll*4+3];
    const float bb0 = b_ih[ll*4+0] + b_hh[ll*4+0];
    const float bb1 = b_ih[ll*4+1] + b_hh[ll*4+1];
    const float bb2 = b_ih[ll*4+2] + b_hh[ll*4+2];
    const float bb3 = b_ih[ll*4+3] + b_hh[ll*4+3];

    float h = h0[ll];
    float c = c0[ll];

    // Lag-2 cross-layer input pipeline registers
    float inp_use = 0.0f, inp_buf = 0.0f;

    int t = -2 * ll;  // timestep this lane processes at current iteration

    // x prefetch queue: 8 deep, 4 consumed per chunk, loads 8..11 ahead
    float q0=0.f,q1=0.f,q2=0.f,q3=0.f,q4=0.f,q5=0.f,q6=0.f,q7=0.f;
    if (lane == 0) {
        float4 a = *reinterpret_cast<const float4*>(x);
        float4 b = *reinterpret_cast<const float4*>(x + 4);
        q0=a.x; q1=a.y; q2=a.z; q3=a.w;
        q4=b.x; q5=b.y; q6=b.z; q7=b.w;
    }

    const int N = kT + 2 * (kL - 1);  // 32772, divisible by 4

#define LSTM_STEP(XV)                                                          \
    {                                                                          \
        float inp = (lane == 0) ? (XV) : inp_use;                              \
        float p0 = fmaf(wi0, inp, bb0);                                        \
        float p1 = fmaf(wi1, inp, bb1);                                        \
        float p2 = fmaf(wi2, inp, bb2);                                        \
        float p3 = fmaf(wi3, inp, bb3);                                        \
        float g0 = fmaf(wh0, h, p0);                                           \
        float g1 = fmaf(wh1, h, p1);                                           \
        float g2 = fmaf(wh2, h, p2);                                           \
        float g3 = fmaf(wh3, h, p3);                                           \
        float ig = f_sigmoid(g0);                                              \
        float fg = f_sigmoid(g1);                                              \
        float gg = f_tanh(g2);                                                 \
        float og = f_sigmoid(g3);                                              \
        float cn = fmaf(fg, c, ig * gg);                                       \
        float hn = og * f_tanh(cn);                                            \
        bool ok = ((unsigned)t) < (unsigned)kT;                                \
        h = ok ? hn : h;                                                       \
        c = ok ? cn : c;                                                       \
        if (lane == 2 && ok) g_outs[t] = hn;                                   \
        inp_use = inp_buf;                                                     \
        inp_buf = __shfl_up_sync(0xFFFFFFFFu, h, 1);                           \
        t++;                                                                   \
    }

    for (int i = 0; i < N; i += 4) {
        // Prefetch x[i+8 .. i+11] (distance ~8 iters ≈ 900 cyc > DRAM latency)
        float4 nx = make_float4(0.f, 0.f, 0.f, 0.f);
        if (lane == 0 && (i + 8) < kT)
            nx = *reinterpret_cast<const float4*>(x + i + 8);

        LSTM_STEP(q0)
        LSTM_STEP(q1)
        LSTM_STEP(q2)
        LSTM_STEP(q3)

        q0 = q4; q1 = q5; q2 = q6; q3 = q7;
        q4 = nx.x; q5 = nx.y; q6 = nx.z; q7 = nx.w;
    }
#undef LSTM_STEP
}

// ---------------------------------------------------------------------------
// GEMV: logits[c] = dot(g_outs, lin_w[c,:]) + lin_b[c]
// 1024 blocks (one row each), 256 threads, float4 coalesced. HBM-bound: 128MB.
// ---------------------------------------------------------------------------
__global__ void __launch_bounds__(256)
gemv_kernel(const float* __restrict__ W, const float* __restrict__ lb)
{
    __shared__ float red[256];
    const int c = blockIdx.x;
    const float4* w4 = reinterpret_cast<const float4*>(W + (size_t)c * kT);
    const float4* o4 = reinterpret_cast<const float4*>(g_outs);

    float acc = 0.0f;
    #pragma unroll 4
    for (int j = threadIdx.x; j < kT / 4; j += 256) {
        float4 w = w4[j];
        float4 o = o4[j];
        acc += w.x * o.x + w.y * o.y + w.z * o.z + w.w * o.w;
    }
    red[threadIdx.x] = acc;
    __syncthreads();
    #pragma unroll
    for (int s = 128; s > 0; s >>= 1) {
        if (threadIdx.x < s) red[threadIdx.x] += red[threadIdx.x + s];
        __syncthreads();
    }
    if (threadIdx.x == 0) g_logits[c] = red[0] + lb[c];
}

// ---------------------------------------------------------------------------
// Softmax over 1024 logits, single block.
// ---------------------------------------------------------------------------
__global__ void __launch_bounds__(kCLS)
softmax_kernel(float* __restrict__ out)
{
    __shared__ float sh[kCLS];
    const int i = threadIdx.x;
    float v = g_logits[i];

    sh[i] = v;
    __syncthreads();
    #pragma unroll
    for (int s = kCLS / 2; s > 0; s >>= 1) {
        if (i < s) sh[i] = fmaxf(sh[i], sh[i + s]);
        __syncthreads();
    }
    float m = sh[0];
    __syncthreads();

    float e = expf(v - m);
    sh[i] = e;
    __syncthreads();
    #pragma unroll
    for (int s = kCLS / 2; s > 0; s >>= 1) {
        if (i < s) sh[i] += sh[i + s];
        __syncthreads();
    }
    out[i] = e / sh[0];
}

// ---------------------------------------------------------------------------
// Launch
// ---------------------------------------------------------------------------
extern "C" void kernel_launch(void* const* d_in, const int* in_sizes, int n_in,
                              void* d_out, int out_size)
{
    const float* x     = (const float*)d_in[0];
    const float* h0    = (const float*)d_in[1];
    const float* c0    = (const float*)d_in[2];
    const float* w_ih  = (const float*)d_in[3];
    const float* w_hh  = (const float*)d_in[4];
    const float* b_ih  = (const float*)d_in[5];
    const float* b_hh  = (const float*)d_in[6];
    const float* lin_w = (const float*)d_in[7];
    const float* lin_b = (const float*)d_in[8];

    lstm_kernel<<<1, 32>>>(x, h0, c0, w_ih, w_hh, b_ih, b_hh);
    gemv_kernel<<<kCLS, 256>>>(lin_w, lin_b);
    softmax_kernel<<<1, kCLS>>>((float*)d_out);
}

// round 3
// speedup vs baseline: 1.3323x; 1.3323x over previous
#include <cuda_runtime.h>
#include <cuda_bf16.h>

// Problem constants
#define kT   32768
#define kL   3
#define kCLS 1024

// Scratch (no cudaMalloc allowed) — device globals
__device__ float g_outs[kT];      // top-layer hidden states
__device__ float g_logits[kCLS];  // pre-softmax logits

#define L2E 1.4426950408889634f

// Single-instruction MUFU wrappers (same accuracy class as __expf/__fdividef,
// ~2 ulp, except tanh.approx which is ~5e-4 and used ONLY on the cell output).
__device__ __forceinline__ float fast_ex2(float x) {
    float y; asm("ex2.approx.f32 %0, %1;" : "=f"(y) : "f"(x)); return y;
}
__device__ __forceinline__ float fast_rcp(float x) {
    float y; asm("rcp.approx.f32 %0, %1;" : "=f"(y) : "f"(x)); return y;
}
__device__ __forceinline__ float fast_tanh(float x) {
    float y; asm("tanh.approx.f32 %0, %1;" : "=f"(y) : "f"(x)); return y;
}

// ---------------------------------------------------------------------------
// LSTM wavefront kernel: 1 warp. Lane l (l<3) runs layer l at timestep
// t = iter - 2*l (lag-2 pipeline: the 26-cycle SHFL cross-layer edge gets a
// full iteration of slack and never binds the recurrence cycle).
//
// Gate math with folded constants (per lane/layer):
//   sigmoid gates k in {0,1,3}:  sig = rcp(1 + ex2(Ak*inp + Bk*h + Ck))
//       Ak = -L2E*wi_k, Bk = -L2E*wh_k, Ck = -L2E*(b_ih+b_hh)
//   g gate (exact tanh):         gg  = 1 - 2*rcp(1 + ex2(A2*inp+B2*h+C2))
//       A2 = +2*L2E*wi_2, ...
//   cell output: hn = og * tanh.approx(cn)   <- only approximation
// ---------------------------------------------------------------------------
__global__ void __launch_bounds__(32, 1)
lstm_kernel(const float* __restrict__ x,
            const float* __restrict__ h0,
            const float* __restrict__ c0,
            const float* __restrict__ w_ih,
            const float* __restrict__ w_hh,
            const float* __restrict__ b_ih,
            const float* __restrict__ b_hh)
{
    const int lane = threadIdx.x & 31;
    const int ll   = (lane < kL) ? lane : (kL - 1);

    const float bb0 = b_ih[ll*4+0] + b_hh[ll*4+0];
    const float bb1 = b_ih[ll*4+1] + b_hh[ll*4+1];
    const float bb2 = b_ih[ll*4+2] + b_hh[ll*4+2];
    const float bb3 = b_ih[ll*4+3] + b_hh[ll*4+3];

    // Folded gate coefficients
    const float A0 = -L2E * w_ih[ll*4+0], B0 = -L2E * w_hh[ll*4+0], C0 = -L2E * bb0;
    const float A1 = -L2E * w_ih[ll*4+1], B1 = -L2E * w_hh[ll*4+1], C1 = -L2E * bb1;
    const float A2 =  2.0f*L2E * w_ih[ll*4+2], B2 = 2.0f*L2E * w_hh[ll*4+2], C2 = 2.0f*L2E * bb2;
    const float A3 = -L2E * w_ih[ll*4+3], B3 = -L2E * w_hh[ll*4+3], C3 = -L2E * bb3;

    float h = h0[ll];
    float c = c0[ll];

    float inp_use = 0.0f, inp_buf = 0.0f;
    int t = -2 * ll;   // this lane's current timestep

    // ---------------- guarded step (prologue/epilogue only) ----------------
#define STEP_G(XV)                                                             \
    {                                                                          \
        float inp = (lane == 0) ? (XV) : inp_use;                              \
        float u0 = fmaf(B0, h, fmaf(A0, inp, C0));                             \
        float u1 = fmaf(B1, h, fmaf(A1, inp, C1));                             \
        float u2 = fmaf(B2, h, fmaf(A2, inp, C2));                             \
        float u3 = fmaf(B3, h, fmaf(A3, inp, C3));                             \
        float ig = fast_rcp(1.0f + fast_ex2(u0));                              \
        float fg = fast_rcp(1.0f + fast_ex2(u1));                              \
        float r2 = fast_rcp(1.0f + fast_ex2(u2));                              \
        float og = fast_rcp(1.0f + fast_ex2(u3));                              \
        float gg = fmaf(-2.0f, r2, 1.0f);                                      \
        float cn = fmaf(ig, gg, fg * c);                                       \
        float hn = og * fast_tanh(cn);                                         \
        bool ok = ((unsigned)t) < (unsigned)kT;                                \
        h = ok ? hn : h;                                                       \
        c = ok ? cn : c;                                                       \
        if (lane == 2 && ok) g_outs[t] = hn;                                   \
        inp_use = inp_buf;                                                     \
        inp_buf = __shfl_up_sync(0xFFFFFFFFu, h, 1);                           \
        t++;                                                                   \
    }

    // ---------------- fast step (steady state, no guards) -------------------
#define STEP_F(XV)                                                             \
    {                                                                          \
        float inp = (lane == 0) ? (XV) : inp_use;                              \
        float u0 = fmaf(B0, h, fmaf(A0, inp, C0));                             \
        float u1 = fmaf(B1, h, fmaf(A1, inp, C1));                             \
        float u2 = fmaf(B2, h, fmaf(A2, inp, C2));                             \
        float u3 = fmaf(B3, h, fmaf(A3, inp, C3));                             \
        float ig = fast_rcp(1.0f + fast_ex2(u0));                              \
        float fg = fast_rcp(1.0f + fast_ex2(u1));                              \
        float r2 = fast_rcp(1.0f + fast_ex2(u2));                              \
        float og = fast_rcp(1.0f + fast_ex2(u3));                              \
        float gg = fmaf(-2.0f, r2, 1.0f);                                      \
        float cn = fmaf(ig, gg, fg * c);                                       \
        float hn = og * fast_tanh(cn);                                         \
        h = hn; c = cn;                                                        \
        if (lane == 2) g_outs[t] = hn;                                         \
        inp_use = inp_buf;                                                     \
        inp_buf = __shfl_up_sync(0xFFFFFFFFu, h, 1);                           \
        t++;                                                                   \
    }

    // Prologue: steps i = 0..7 (guarded; lanes 1/2 warm up)
    {
        float p[8] = {0,0,0,0,0,0,0,0};
        if (lane == 0) {
            float4 a = *reinterpret_cast<const float4*>(x);
            float4 b = *reinterpret_cast<const float4*>(x + 4);
            p[0]=a.x; p[1]=a.y; p[2]=a.z; p[3]=a.w;
            p[4]=b.x; p[5]=b.y; p[6]=b.z; p[7]=b.w;
        }
        STEP_G(p[0]) STEP_G(p[1]) STEP_G(p[2]) STEP_G(p[3])
        STEP_G(p[4]) STEP_G(p[5]) STEP_G(p[6]) STEP_G(p[7])
    }

    // Rolling x queue: q holds x[i .. i+15] at the top of each main block.
    float q[16];
    if (lane == 0) {
        #pragma unroll
        for (int j = 0; j < 4; j++) {
            float4 v = *reinterpret_cast<const float4*>(x + 8 + 4*j);
            q[4*j+0]=v.x; q[4*j+1]=v.y; q[4*j+2]=v.z; q[4*j+3]=v.w;
        }
    } else {
        #pragma unroll
        for (int j = 0; j < 16; j++) q[j] = 0.0f;
    }

    // Main: i = 8 .. 32767, 8 steps/block, guard-free
    for (int i = 8; i < kT; i += 8) {
        float nx[8];
        #pragma unroll
        for (int j = 0; j < 8; j++) nx[j] = 0.0f;
        if (lane == 0 && (i + 24) <= kT) {
            float4 a = *reinterpret_cast<const float4*>(x + i + 16);
            float4 b = *reinterpret_cast<const float4*>(x + i + 20);
            nx[0]=a.x; nx[1]=a.y; nx[2]=a.z; nx[3]=a.w;
            nx[4]=b.x; nx[5]=b.y; nx[6]=b.z; nx[7]=b.w;
        }

        STEP_F(q[0]) STEP_F(q[1]) STEP_F(q[2]) STEP_F(q[3])
        STEP_F(q[4]) STEP_F(q[5]) STEP_F(q[6]) STEP_F(q[7])

        #pragma unroll
        for (int j = 0; j < 8; j++) { q[j] = q[j+8]; q[j+8] = nx[j]; }
    }

    // Epilogue: 4 guarded steps to drain lanes 1 and 2
    STEP_G(0.0f) STEP_G(0.0f) STEP_G(0.0f) STEP_G(0.0f)

#undef STEP_G
#undef STEP_F
}

// ---------------------------------------------------------------------------
// GEMV: logits[c] = dot(g_outs, lin_w[c,:]) + lin_b[c]   (HBM-bound, 128 MB)
// ---------------------------------------------------------------------------
__global__ void __launch_bounds__(256)
gemv_kernel(const float* __restrict__ W, const float* __restrict__ lb)
{
    __shared__ float red[256];
    const int c = blockIdx.x;
    const float4* w4 = reinterpret_cast<const float4*>(W + (size_t)c * kT);
    const float4* o4 = reinterpret_cast<const float4*>(g_outs);

    float acc = 0.0f;
    #pragma unroll 4
    for (int j = threadIdx.x; j < kT / 4; j += 256) {
        float4 w = w4[j];
        float4 o = o4[j];
        acc += w.x * o.x + w.y * o.y + w.z * o.z + w.w * o.w;
    }
    red[threadIdx.x] = acc;
    __syncthreads();
    #pragma unroll
    for (int s = 128; s > 0; s >>= 1) {
        if (threadIdx.x < s) red[threadIdx.x] += red[threadIdx.x + s];
        __syncthreads();
    }
    if (threadIdx.x == 0) g_logits[c] = red[0] + lb[c];
}

// ---------------------------------------------------------------------------
// Softmax over 1024 logits, single block.
// ---------------------------------------------------------------------------
__global__ void __launch_bounds__(kCLS)
softmax_kernel(float* __restrict__ out)
{
    __shared__ float sh[kCLS];
    const int i = threadIdx.x;
    float v = g_logits[i];

    sh[i] = v;
    __syncthreads();
    #pragma unroll
    for (int s = kCLS / 2; s > 0; s >>= 1) {
        if (i < s) sh[i] = fmaxf(sh[i], sh[i + s]);
        __syncthreads();
    }
    float m = sh[0];
    __syncthreads();

    float e = expf(v - m);
    sh[i] = e;
    __syncthreads();
    #pragma unroll
    for (int s = kCLS / 2; s > 0; s >>= 1) {
        if (i < s) sh[i] += sh[i + s];
        __syncthreads();
    }
    out[i] = e / sh[0];
}

// ---------------------------------------------------------------------------
// Launch
// ---------------------------------------------------------------------------
extern "C" void kernel_launch(void* const* d_in, const int* in_sizes, int n_in,
                              void* d_out, int out_size)
{
    const float* x     = (const float*)d_in[0];
    const float* h0    = (const float*)d_in[1];
    const float* c0    = (const float*)d_in[2];
    const float* w_ih  = (const float*)d_in[3];
    const float* w_hh  = (const float*)d_in[4];
    const float* b_ih  = (const float*)d_in[5];
    const float* b_hh  = (const float*)d_in[6];
    const float* lin_w = (const float*)d_in[7];
    const float* lin_b = (const float*)d_in[8];

    lstm_kernel<<<1, 32>>>(x, h0, c0, w_ih, w_hh, b_ih, b_hh);
    gemv_kernel<<<kCLS, 256>>>(lin_w, lin_b);
    softmax_kernel<<<1, kCLS>>>((float*)d_out);
}

// round 4
// speedup vs baseline: 2.1806x; 1.6367x over previous
#include <cuda_runtime.h>
#include <cuda_bf16.h>

// Problem constants
#define kT   32768
#define kL   3
#define kCLS 1024

// Scratch (no cudaMalloc allowed) — device globals
__device__ float g_outs[kT];      // top-layer hidden states
__device__ float g_logits[kCLS];  // pre-softmax logits

// Hardware MUFU.TANH — measured (R2) to contribute <1e-6 rel err over the
// full 32768-step recurrence, so ALL activations now route through it.
__device__ __forceinline__ float fast_tanh(float x) {
    float y; asm("tanh.approx.f32 %0, %1;" : "=f"(y) : "f"(x)); return y;
}

// ---------------------------------------------------------------------------
// LSTM wavefront kernel: 1 warp. Lane l (l<3) runs layer l at timestep
// t = iter - 2*l (lag-2 pipeline: the 26-cycle SHFL cross-layer edge gets a
// full iteration of slack and never binds the recurrence cycle).
//
// Gate math (per lane/layer), everything one MUFU.TANH deep:
//   sigmoid gates k in {0,1,3}:  sig = 0.5*tanh(0.5*(w·inp + wh·h + b)) + 0.5
//       -> u = Ak*inp + Bk*h + Ck with Ak = 0.5*wi_k etc., sig = fma(th,0.5,0.5)
//   g gate:                      gg  = tanh(w·inp + wh·h + b)
//   cn = fma(fg, c, ig*gg);  hn = og * tanh(cn)
// Critical cycle ≈ 56-60 cyc; MUFU pressure 5*8 = 40 cyc (non-binding).
// ---------------------------------------------------------------------------
__global__ void __launch_bounds__(32, 1)
lstm_kernel(const float* __restrict__ x,
            const float* __restrict__ h0,
            const float* __restrict__ c0,
            const float* __restrict__ w_ih,
            const float* __restrict__ w_hh,
            const float* __restrict__ b_ih,
            const float* __restrict__ b_hh)
{
    const int lane = threadIdx.x & 31;
    const int ll   = (lane < kL) ? lane : (kL - 1);

    const float bb0 = b_ih[ll*4+0] + b_hh[ll*4+0];
    const float bb1 = b_ih[ll*4+1] + b_hh[ll*4+1];
    const float bb2 = b_ih[ll*4+2] + b_hh[ll*4+2];
    const float bb3 = b_ih[ll*4+3] + b_hh[ll*4+3];

    // Folded gate coefficients: 0.5x for sigmoid gates (tanh identity), 1x for g
    const float A0 = 0.5f * w_ih[ll*4+0], B0 = 0.5f * w_hh[ll*4+0], C0 = 0.5f * bb0;
    const float A1 = 0.5f * w_ih[ll*4+1], B1 = 0.5f * w_hh[ll*4+1], C1 = 0.5f * bb1;
    const float A2 =        w_ih[ll*4+2], B2 =        w_hh[ll*4+2], C2 =        bb2;
    const float A3 = 0.5f * w_ih[ll*4+3], B3 = 0.5f * w_hh[ll*4+3], C3 = 0.5f * bb3;

    float h = h0[ll];
    float c = c0[ll];

    float inp_use = 0.0f, inp_buf = 0.0f;
    int t = -2 * ll;   // per-lane timestep counter (guarded steps only)

    // ---------------- guarded step (prologue/epilogue only) ----------------
#define STEP_G(XV)                                                             \
    {                                                                          \
        float inp = (lane == 0) ? (XV) : inp_use;                              \
        float u0 = fmaf(B0, h, fmaf(A0, inp, C0));                             \
        float u1 = fmaf(B1, h, fmaf(A1, inp, C1));                             \
        float u2 = fmaf(B2, h, fmaf(A2, inp, C2));                             \
        float u3 = fmaf(B3, h, fmaf(A3, inp, C3));                             \
        float th0 = fast_tanh(u0);                                             \
        float th1 = fast_tanh(u1);                                             \
        float gg  = fast_tanh(u2);                                             \
        float th3 = fast_tanh(u3);                                             \
        float ig = fmaf(th0, 0.5f, 0.5f);                                      \
        float fg = fmaf(th1, 0.5f, 0.5f);                                      \
        float og = fmaf(th3, 0.5f, 0.5f);                                      \
        float cn = fmaf(fg, c, ig * gg);                                       \
        float hn = og * fast_tanh(cn);                                         \
        bool ok = ((unsigned)t) < (unsigned)kT;                                \
        h = ok ? hn : h;                                                       \
        c = ok ? cn : c;                                                       \
        if (lane == 2 && ok) g_outs[t] = hn;                                   \
        inp_use = inp_buf;                                                     \
        inp_buf = __shfl_up_sync(0xFFFFFFFFu, h, 1);                           \
        t++;                                                                   \
    }

    // -------- fast step (steady state): no guards, static store offset ------
#define STEP_F(XV, TIDX)                                                       \
    {                                                                          \
        float inp = (lane == 0) ? (XV) : inp_use;                              \
        float u0 = fmaf(B0, h, fmaf(A0, inp, C0));                             \
        float u1 = fmaf(B1, h, fmaf(A1, inp, C1));                             \
        float u2 = fmaf(B2, h, fmaf(A2, inp, C2));                             \
        float u3 = fmaf(B3, h, fmaf(A3, inp, C3));                             \
        float th0 = fast_tanh(u0);                                             \
        float th1 = fast_tanh(u1);                                             \
        float gg  = fast_tanh(u2);                                             \
        float th3 = fast_tanh(u3);                                             \
        float ig = fmaf(th0, 0.5f, 0.5f);                                      \
        float fg = fmaf(th1, 0.5f, 0.5f);                                      \
        float og = fmaf(th3, 0.5f, 0.5f);                                      \
        float cn = fmaf(fg, c, ig * gg);                                       \
        float hn = og * fast_tanh(cn);                                         \
        h = hn; c = cn;                                                        \
        if (lane == 2) g_outs[TIDX] = hn;                                      \
        inp_use = inp_buf;                                                     \
        inp_buf = __shfl_up_sync(0xFFFFFFFFu, h, 1);                           \
    }

    // Prologue: global steps 0..7 (guarded; lanes 1/2 warm up)
    {
        float p[8] = {0,0,0,0,0,0,0,0};
        if (lane == 0) {
            float4 a = *reinterpret_cast<const float4*>(x);
            float4 b = *reinterpret_cast<const float4*>(x + 4);
            p[0]=a.x; p[1]=a.y; p[2]=a.z; p[3]=a.w;
            p[4]=b.x; p[5]=b.y; p[6]=b.z; p[7]=b.w;
        }
        STEP_G(p[0]) STEP_G(p[1]) STEP_G(p[2]) STEP_G(p[3])
        STEP_G(p[4]) STEP_G(p[5]) STEP_G(p[6]) STEP_G(p[7])
    }

    // Rolling x queue: q holds x[i .. i+15] at the top of each main block.
    float q[16];
    if (lane == 0) {
        #pragma unroll
        for (int j = 0; j < 4; j++) {
            float4 v = *reinterpret_cast<const float4*>(x + 8 + 4*j);
            q[4*j+0]=v.x; q[4*j+1]=v.y; q[4*j+2]=v.z; q[4*j+3]=v.w;
        }
    } else {
        #pragma unroll
        for (int j = 0; j < 16; j++) q[j] = 0.0f;
    }

    // Main: global steps 8 .. 32767, 8 steps/block, guard-free.
    // Lane 2 (layer 2) at global step i runs timestep i-4.
    for (int i = 8; i < kT; i += 8) {
        float nx[8];
        #pragma unroll
        for (int j = 0; j < 8; j++) nx[j] = 0.0f;
        if (lane == 0 && (i + 24) <= kT) {
            float4 a = *reinterpret_cast<const float4*>(x + i + 16);
            float4 b = *reinterpret_cast<const float4*>(x + i + 20);
            nx[0]=a.x; nx[1]=a.y; nx[2]=a.z; nx[3]=a.w;
            nx[4]=b.x; nx[5]=b.y; nx[6]=b.z; nx[7]=b.w;
        }

        STEP_F(q[0], i - 4 + 0) STEP_F(q[1], i - 4 + 1)
        STEP_F(q[2], i - 4 + 2) STEP_F(q[3], i - 4 + 3)
        STEP_F(q[4], i - 4 + 4) STEP_F(q[5], i - 4 + 5)
        STEP_F(q[6], i - 4 + 6) STEP_F(q[7], i - 4 + 7)

        #pragma unroll
        for (int j = 0; j < 8; j++) { q[j] = q[j+8]; q[j+8] = nx[j]; }
    }

    // Epilogue: 4 guarded steps to drain lanes 1 and 2 (lane2 t: 32764..32767)
    t = (lane == 0) ? kT : ((lane == 1) ? kT - 2 : kT - 4);
    STEP_G(0.0f) STEP_G(0.0f) STEP_G(0.0f) STEP_G(0.0f)

#undef STEP_G
#undef STEP_F
}

// ---------------------------------------------------------------------------
// GEMV: logits[c] = dot(g_outs, lin_w[c,:]) + lin_b[c]   (HBM-bound, 128 MB)
// ---------------------------------------------------------------------------
__global__ void __launch_bounds__(256)
gemv_kernel(const float* __restrict__ W, const float* __restrict__ lb)
{
    __shared__ float red[256];
    const int c = blockIdx.x;
    const float4* w4 = reinterpret_cast<const float4*>(W + (size_t)c * kT);
    const float4* o4 = reinterpret_cast<const float4*>(g_outs);

    float acc = 0.0f;
    #pragma unroll 4
    for (int j = threadIdx.x; j < kT / 4; j += 256) {
        float4 w = w4[j];
        float4 o = o4[j];
        acc += w.x * o.x + w.y * o.y + w.z * o.z + w.w * o.w;
    }
    red[threadIdx.x] = acc;
    __syncthreads();
    #pragma unroll
    for (int s = 128; s > 0; s >>= 1) {
        if (threadIdx.x < s) red[threadIdx.x] += red[threadIdx.x + s];
        __syncthreads();
    }
    if (threadIdx.x == 0) g_logits[c] = red[0] + lb[c];
}

// ---------------------------------------------------------------------------
// Softmax over 1024 logits, single block.
// ---------------------------------------------------------------------------
__global__ void __launch_bounds__(kCLS)
softmax_kernel(float* __restrict__ out)
{
    __shared__ float sh[kCLS];
    const int i = threadIdx.x;
    float v = g_logits[i];

    sh[i] = v;
    __syncthreads();
    #pragma unroll
    for (int s = kCLS / 2; s > 0; s >>= 1) {
        if (i < s) sh[i] = fmaxf(sh[i], sh[i + s]);
        __syncthreads();
    }
    float m = sh[0];
    __syncthreads();

    float e = expf(v - m);
    sh[i] = e;
    __syncthreads();
    #pragma unroll
    for (int s = kCLS / 2; s > 0; s >>= 1) {
        if (i < s) sh[i] += sh[i + s];
        __syncthreads();
    }
    out[i] = e / sh[0];
}

// ---------------------------------------------------------------------------
// Launch
// ---------------------------------------------------------------------------
extern "C" void kernel_launch(void* const* d_in, const int* in_sizes, int n_in,
                              void* d_out, int out_size)
{
    const float* x     = (const float*)d_in[0];
    const float* h0    = (const float*)d_in[1];
    const float* c0    = (const float*)d_in[2];
    const float* w_ih  = (const float*)d_in[3];
    const float* w_hh  = (const float*)d_in[4];
    const float* b_ih  = (const float*)d_in[5];
    const float* b_hh  = (const float*)d_in[6];
    const float* lin_w = (const float*)d_in[7];
    const float* lin_b = (const float*)d_in[8];

    lstm_kernel<<<1, 32>>>(x, h0, c0, w_ih, w_hh, b_ih, b_hh);
    gemv_kernel<<<kCLS, 256>>>(lin_w, lin_b);
    softmax_kernel<<<1, kCLS>>>((float*)d_out);
}